// round 14
// baseline (speedup 1.0000x reference)
#include <cuda_runtime.h>
#include <cuda_fp16.h>

typedef unsigned long long u64;
typedef unsigned int u32;
#define BATCH 131072

// inter-phase state: concat layout [b][96], enc at 0..63, cent at 64..95
__device__ float g_h0[(size_t)BATCH * 96];
__device__ float g_c0[(size_t)BATCH * 96];

__device__ __forceinline__ float ex2f(float x){ float y; asm("ex2.approx.f32 %0, %1;" : "=f"(y) : "f"(x)); return y; }
__device__ __forceinline__ float rcpf(float x){ float y; asm("rcp.approx.f32 %0, %1;" : "=f"(y) : "f"(x)); return y; }
__device__ __forceinline__ float sigmf(float x){ return rcpf(1.0f + ex2f(-1.4426950408889634f * x)); }
__device__ __forceinline__ float tanhf_(float x){ return 1.0f - 2.0f * rcpf(1.0f + ex2f(2.8853900817779268f * x)); }

__device__ __forceinline__ void ffma2(u64 &d, u64 a, u64 b){
    asm("fma.rn.f32x2 %0, %1, %2, %0;" : "+l"(d) : "l"(a), "l"(b));
}
__device__ __forceinline__ float red2(u64 a){
    float lo, hi; asm("mov.b64 {%0, %1}, %2;" : "=f"(lo), "=f"(hi) : "l"(a)); return lo + hi;
}
__device__ __forceinline__ u64 pk2(float x, float y){
    u64 r; asm("mov.b64 %0, {%1, %2};" : "=l"(r) : "f"(x), "f"(y)); return r;
}
__device__ __forceinline__ u32 smem_u32(const void* p){
    u32 a; asm("{ .reg .u64 t; cvta.to.shared.u64 t, %1; cvt.u32.u64 %0, t; }" : "=r"(a) : "l"(p)); return a;
}
__device__ __forceinline__ void ldsm4(u32 &r0, u32 &r1, u32 &r2, u32 &r3, u32 addr){
    asm volatile("ldmatrix.sync.aligned.m8n8.x4.shared.b16 {%0,%1,%2,%3}, [%4];"
        : "=r"(r0), "=r"(r1), "=r"(r2), "=r"(r3) : "r"(addr));
}
__device__ __forceinline__ void mma_f16(float &d0, float &d1, float &d2, float &d3,
                                        const u32* a, u32 b0, u32 b1){
    asm volatile("mma.sync.aligned.m16n8k16.row.col.f32.f16.f16.f32 "
        "{%0,%1,%2,%3}, {%4,%5,%6,%7}, {%8,%9}, {%0,%1,%2,%3};"
        : "+f"(d0), "+f"(d1), "+f"(d2), "+f"(d3)
        : "r"(a[0]), "r"(a[1]), "r"(a[2]), "r"(a[3]), "r"(b0), "r"(b1));
}

// ---------------------------------------------------------------------------
// cent / enc recurrent phase on HMMA, 3-pass (W split hi/lo fp16).
// x-projection AND bias folded into the MMA contraction:
//   h_ext = [h; x0; x1; 1],  W_ext = [Whh; Wih_c0; Wih_c1; bias]
// Gates come out of the tensor core finished. Epilogue = shfl + gate math
// + h store only. Double-buffered h, one barrier per step.
// ---------------------------------------------------------------------------
template<int H, int T, int OFF, int MINB>
__global__ __launch_bounds__(512, MINB)
void lstm_rec_mma(const float* __restrict__ x_g,
                  const float* __restrict__ Wih, const float* __restrict__ Whh,
                  const float* __restrict__ bih, const float* __restrict__ bhh)
{
    constexpr int G     = 4 * H;
    constexpr int NE    = 64;
    constexpr int KCE   = (H + 3 + 15) / 16;  // k16 chunks incl x(2)+bias(1)
    constexpr int KP    = KCE * 16 + 8;       // halves per row
    constexpr int WROWB = 2 * KP;             // bytes per row
    constexpr int NPAIR = H / 16;             // n8-tile pairs per warp
    constexpr int HBUF  = NE * WROWB;         // one h buffer, bytes
    // SMEM byte offsets
    constexpr int SWHI = 0;
    constexpr int SWLO = SWHI + G * KP * 2;
    constexpr int SHHI = SWLO + G * KP * 2;   // 2 buffers
    constexpr int SHLO = SHHI + 2 * HBUF;     // 2 buffers

    extern __shared__ char smc[];
    const u32 smb = smem_u32(smc);

    const int tid = threadIdx.x;
    const size_t b0 = (size_t)blockIdx.x * NE;

    // ---- W_ext fill: torch row = g*H+j -> interleaved col r = 4j+g ----
    for (int i = tid; i < G * KP; i += 512){
        int r = i / KP, k = i % KP;
        int j = r >> 2, g = r & 3;
        int trow = g * H + j;
        float w;
        if (k < H)            w = Whh[trow * H + k];
        else if (k == H)      w = Wih[trow * 2];
        else if (k == H + 1)  w = Wih[trow * 2 + 1];
        else if (k == H + 2)  w = bih[trow] + bhh[trow];
        else                  w = 0.0f;
        __half hi = __float2half_rn(w);
        __half lo = __float2half_rn(w - __half2float(hi));
        *(__half*)(smc + SWHI + i * 2) = hi;
        *(__half*)(smc + SWLO + i * 2) = lo;
    }
    // h buffers: zero everything (both buffers, hi+lo)
    for (int i = tid; i < 2 * NE * KP; i += 512){
        *(__half*)(smc + SHHI + i * 2) = __float2half_rn(0.f);
        *(__half*)(smc + SHLO + i * 2) = __float2half_rn(0.f);
    }
    __syncthreads();
    // const-1 slot (both buffers) + x(t=0) into buffer 0
    if (tid < NE){
        const int e = tid;
        *(__half*)(smc + SHHI + (e * KP + H + 2) * 2) = __float2half_rn(1.0f);
        *(__half*)(smc + SHHI + HBUF + (e * KP + H + 2) * 2) = __float2half_rn(1.0f);
        float2 xv = *(const float2*)(x_g + (b0 + e) * (size_t)(2 * T));
        __half h0 = __float2half_rn(xv.x), h1 = __float2half_rn(xv.y);
        *(__half2*)(smc + SHHI + (e * KP + H) * 2) = __halves2half2(h0, h1);
        *(__half2*)(smc + SHLO + (e * KP + H) * 2) =
            __halves2half2(__float2half_rn(xv.x - __half2float(h0)),
                           __float2half_rn(xv.y - __half2float(h1)));
    }

    const int wid = tid >> 5, lane = tid & 31;
    const int cg = wid & 3, rg = wid >> 2;
    const int e0 = rg * 16, colbase = cg * H;
    const int tg = lane & 3, gq = lane >> 2;
    const bool is_even = (tg & 1) == 0;
    const int el = e0 + gq + (is_even ? 0 : 8);   // this lane's element
    const bool xw = (cg == 0 && tg < 2);          // x-writer lane

    // ldmatrix per-lane addresses (buffer 0 bases)
    const int a_row = e0 + (lane & 7) + ((lane >> 3) & 1) * 8;
    const u32 a_koff = ((lane >> 4) & 1) * 16;
    const u32 ah_base = smb + SHHI + (u32)a_row * WROWB + a_koff;
    const u32 al_base = smb + SHLO + (u32)a_row * WROWB + a_koff;
    const int b4_row = colbase + ((lane >> 4) << 3) + (lane & 7);
    const u32 b4_koff = ((lane >> 3) & 1) * 16;
    const u32 bh4_base = smb + SWHI + (u32)b4_row * WROWB + b4_koff;
    const u32 bl4_base = smb + SWLO + (u32)b4_row * WROWB + b4_koff;

    constexpr int NCELL = H / 8;
    float c[NCELL];
    #pragma unroll
    for (int n0 = 0; n0 < NCELL; n0++) c[n0] = 0.f;

    __syncthreads();

    for (int t = 0; t < T; t++){
        const u32 roff = (u32)(t & 1) * HBUF;        // read buffer
        const u32 woff = (u32)((t + 1) & 1) * HBUF;  // write buffer

        // prefetch next step's x (designated lanes only)
        float2 xn = make_float2(0.f, 0.f);
        if (xw && t + 1 < T)
            xn = *(const float2*)(x_g + (b0 + el) * (size_t)(2 * T) + 2 * (t + 1));

        // A fragments (h_ext hi/lo) from read buffer
        u32 ahi[KCE][4], alo[KCE][4];
        #pragma unroll
        for (int kc = 0; kc < KCE; kc++){
            ldsm4(ahi[kc][0], ahi[kc][1], ahi[kc][2], ahi[kc][3], ah_base + roff + kc * 32);
            ldsm4(alo[kc][0], alo[kc][1], alo[kc][2], alo[kc][3], al_base + roff + kc * 32);
        }

        #pragma unroll
        for (int p = 0; p < NPAIR; p++){
            float d[2][4];
            #pragma unroll
            for (int h2 = 0; h2 < 2; h2++)
                #pragma unroll
                for (int r2 = 0; r2 < 4; r2++) d[h2][r2] = 0.f;
            const u32 bhp = bh4_base + (u32)(p * 16) * WROWB;
            const u32 blp = bl4_base + (u32)(p * 16) * WROWB;
            #pragma unroll
            for (int kc = 0; kc < KCE; kc++){
                u32 h0q, h1q, h2q, h3q, l0q, l1q, l2q, l3q;
                ldsm4(h0q, h1q, h2q, h3q, bhp + kc * 32);
                ldsm4(l0q, l1q, l2q, l3q, blp + kc * 32);
                mma_f16(d[0][0], d[0][1], d[0][2], d[0][3], ahi[kc], h0q, h1q);
                mma_f16(d[0][0], d[0][1], d[0][2], d[0][3], alo[kc], h0q, h1q);
                mma_f16(d[0][0], d[0][1], d[0][2], d[0][3], ahi[kc], l0q, l1q);
                mma_f16(d[1][0], d[1][1], d[1][2], d[1][3], ahi[kc], h2q, h3q);
                mma_f16(d[1][0], d[1][1], d[1][2], d[1][3], alo[kc], h2q, h3q);
                mma_f16(d[1][0], d[1][1], d[1][2], d[1][3], ahi[kc], l2q, l3q);
            }
            #pragma unroll
            for (int h2 = 0; h2 < 2; h2++){
                const int n0 = 2 * p + h2;
                float d0 = d[h2][0], d1 = d[h2][1], d2 = d[h2][2], d3 = d[h2][3];
                // parity-select exchange: even lane -> eA's 4 gates, odd -> eB's
                float ra = __shfl_xor_sync(0xffffffffu, is_even ? d2 : d0, 1);
                float rb = __shfl_xor_sync(0xffffffffu, is_even ? d3 : d1, 1);
                float gi = is_even ? d0 : ra;
                float gf = is_even ? d1 : rb;
                float gg = is_even ? ra : d2;
                float go = is_even ? rb : d3;
                const int r4 = colbase + n0 * 8 + (tg >> 1) * 4;   // = 4j
                const int j = r4 >> 2;
                float cn = sigmf(gf) * c[n0] + sigmf(gi) * tanhf_(gg);
                float hv = sigmf(go) * tanhf_(cn);
                c[n0] = cn;
                __half hh = __float2half_rn(hv);
                *(__half*)(smc + SHHI + woff + (el * KP + j) * 2) = hh;
                *(__half*)(smc + SHLO + woff + (el * KP + j) * 2) = __float2half_rn(hv - __half2float(hh));
                if (t == T - 1){
                    g_h0[(b0 + el) * 96 + OFF + j] = hv;
                    g_c0[(b0 + el) * 96 + OFF + j] = cn;
                }
            }
        }
        // write x_{t+1} into the write buffer (designated lanes)
        if (xw && t + 1 < T){
            __half h0 = __float2half_rn(xn.x), h1 = __float2half_rn(xn.y);
            *(__half2*)(smc + SHHI + woff + (el * KP + H) * 2) = __halves2half2(h0, h1);
            *(__half2*)(smc + SHLO + woff + (el * KP + H) * 2) =
                __halves2half2(__float2half_rn(xn.x - __half2float(h0)),
                               __float2half_rn(xn.y - __half2float(h1)));
        }
        __syncthreads();   // single barrier per step
    }
}

// ---------------------------------------------------------------------------
// decoder on HMMA, fp16 2-pass, NE=64 elems/CTA, both-lane epilogue,
// double-buffered h (one barrier per step). Unchanged from round 13.
// ---------------------------------------------------------------------------
#define DNT 512
#define SW_HI   0          // W_hi  [384][104] fp16          (79,872)
#define SH_HI   79872      // h_hi  2 x [64][104] fp16       (26,624)
#define SH_LO   106496     // h_lo  2 x [64][104] fp16       (26,624)
#define S_BSD   133120     // bias  [384] f32                (1,536)
#define S_WEX   134656     // [96] f32
#define S_WEY   135040     // [96] f32
#define SM_TOT  135424
#define WROW    208
#define DHBUF   (64 * WROW)   // 13,312 bytes per h buffer

__global__ __launch_bounds__(DNT, 1)
void lstm_dec_mma(const float* __restrict__ Wih, const float* __restrict__ Whh,
                  const float* __restrict__ bih, const float* __restrict__ bhh,
                  const float* __restrict__ Wemb, const float* __restrict__ bemb,
                  float* __restrict__ out)
{
    extern __shared__ char smc[];
    float* bsd  = (float*)(smc + S_BSD);
    float* wex  = (float*)(smc + S_WEX);
    float* wey  = (float*)(smc + S_WEY);
    const u32 smb = smem_u32(smc);

    const int tid = threadIdx.x;
    const size_t b0 = (size_t)blockIdx.x * 64;

    for (int i = tid; i < 384 * 96; i += DNT){
        int trow = i / 96, k = i % 96;
        int g = trow / 96, j = trow % 96;
        float w = Wih[i] + Whh[i];
        int r = 4 * j + g;
        *(__half*)(smc + SW_HI + (r * 104 + k) * 2) = __float2half_rn(w);
    }
    for (int i = tid; i < 384; i += DNT){
        int g = i / 96, j = i % 96;
        bsd[4 * j + g] = bih[i] + bhh[i];
    }
    for (int i = tid; i < 96; i += DNT){ wex[i] = Wemb[i]; wey[i] = Wemb[96 + i]; }

    // h0 into buffer 0
    for (int i = tid; i < 64 * 96; i += DNT){
        int e = i / 96, j = i % 96;
        float v = g_h0[(b0 + e) * 96 + j];
        __half hi = __float2half_rn(v);
        __half lo = __float2half_rn(v - __half2float(hi));
        *(__half*)(smc + SH_HI + (e * 104 + j) * 2) = hi;
        *(__half*)(smc + SH_LO + (e * 104 + j) * 2) = lo;
    }

    const int wid = tid >> 5, lane = tid & 31;
    const int cg = wid & 3, rg = wid >> 2;
    const int e0 = rg * 16, colbase = cg * 96;
    const int tg = lane & 3, gq = lane >> 2;
    const bool is_even = (tg & 1) == 0;
    const int el = e0 + gq + (is_even ? 0 : 8);

    const int a_row = e0 + (lane & 7) + ((lane >> 3) & 1) * 8;
    const u32 a_koff = ((lane >> 4) & 1) * 16;
    const u32 ah_base = smb + SH_HI + (u32)a_row * WROW + a_koff;
    const u32 al_base = smb + SH_LO + (u32)a_row * WROW + a_koff;
    const int b4_row = colbase + ((lane >> 4) << 3) + (lane & 7);
    const u32 b4_koff = ((lane >> 3) & 1) * 16;
    const u32 b4_base = smb + SW_HI + (u32)b4_row * WROW + b4_koff;

    float c[12];
    #pragma unroll
    for (int n0 = 0; n0 < 12; n0++){
        int j = cg * 24 + 2 * n0 + (tg >> 1);
        c[n0] = g_c0[(b0 + el) * 96 + j];
    }
    const float bex = bemb[0], bey = bemb[1];
    __syncthreads();

    for (int t = 0; t < 30; t++){
        const u32 roff = (u32)(t & 1) * DHBUF;
        const u32 woff = (u32)((t + 1) & 1) * DHBUF;

        u32 ahi[6][4], alo[6][4];
        #pragma unroll
        for (int kc = 0; kc < 6; kc++){
            ldsm4(ahi[kc][0], ahi[kc][1], ahi[kc][2], ahi[kc][3], ah_base + roff + kc * 32);
            ldsm4(alo[kc][0], alo[kc][1], alo[kc][2], alo[kc][3], al_base + roff + kc * 32);
        }

        #pragma unroll
        for (int p = 0; p < 6; p++){
            float d[2][4];
            #pragma unroll
            for (int h2 = 0; h2 < 2; h2++)
                #pragma unroll
                for (int r2 = 0; r2 < 4; r2++) d[h2][r2] = 0.f;
            const u32 bp = b4_base + (u32)(p * 16) * WROW;
            #pragma unroll
            for (int kc = 0; kc < 6; kc++){
                u32 bq0, bq1, bq2, bq3;
                ldsm4(bq0, bq1, bq2, bq3, bp + kc * 32);
                mma_f16(d[0][0], d[0][1], d[0][2], d[0][3], ahi[kc], bq0, bq1);
                mma_f16(d[0][0], d[0][1], d[0][2], d[0][3], alo[kc], bq0, bq1);
                mma_f16(d[1][0], d[1][1], d[1][2], d[1][3], ahi[kc], bq2, bq3);
                mma_f16(d[1][0], d[1][1], d[1][2], d[1][3], alo[kc], bq2, bq3);
            }
            #pragma unroll
            for (int h2 = 0; h2 < 2; h2++){
                const int n0 = 2 * p + h2;
                float d0 = d[h2][0], d1 = d[h2][1], d2 = d[h2][2], d3 = d[h2][3];
                float ra = __shfl_xor_sync(0xffffffffu, is_even ? d2 : d0, 1);
                float rb = __shfl_xor_sync(0xffffffffu, is_even ? d3 : d1, 1);
                float gi_ = is_even ? d0 : ra;
                float gf_ = is_even ? d1 : rb;
                float gg_ = is_even ? ra : d2;
                float go_ = is_even ? rb : d3;
                const int r4 = colbase + n0 * 8 + (tg >> 1) * 4;
                const int j = r4 >> 2;
                float cn = sigmf(gf_ + bsd[r4+1]) * c[n0] + sigmf(gi_ + bsd[r4]) * tanhf_(gg_ + bsd[r4+2]);
                float hv = sigmf(go_ + bsd[r4+3]) * tanhf_(cn);
                c[n0] = cn;
                __half hh = __float2half_rn(hv);
                *(__half*)(smc + SH_HI + woff + (el * 104 + j) * 2) = hh;
                *(__half*)(smc + SH_LO + woff + (el * 104 + j) * 2) = __float2half_rn(hv - __half2float(hh));
            }
        }
        __syncthreads();   // single barrier: h_t visible for pos + next step

        if (tid < 64){
            u64 ax = 0ULL, ay = 0ULL;
            const __half2* ph = (const __half2*)(smc + SH_HI + woff + tid * WROW);
            const __half2* pl = (const __half2*)(smc + SH_LO + woff + tid * WROW);
            #pragma unroll 8
            for (int kk = 0; kk < 48; kk++){
                float2 hi = __half22float2(ph[kk]);
                float2 lo = __half22float2(pl[kk]);
                u64 hd = pk2(hi.x + lo.x, hi.y + lo.y);
                ffma2(ax, hd, *(const u64*)&wex[2 * kk]);
                ffma2(ay, hd, *(const u64*)&wey[2 * kk]);
            }
            float2 o; o.x = red2(ax) + bex; o.y = red2(ay) + bey;
            *(float2*)(out + (b0 + tid) * 60 + 2 * t) = o;
        }
    }
}

extern "C" void kernel_launch(void* const* d_in, const int* in_sizes, int n_in,
                              void* d_out, int out_size)
{
    (void)n_in; (void)out_size;
    const float* traj  = (const float*)d_in[0];
    const float* cent  = (const float*)d_in[1];
    const float* Wih_c = (const float*)d_in[2];
    const float* Whh_c = (const float*)d_in[3];
    const float* bih_c = (const float*)d_in[4];
    const float* bhh_c = (const float*)d_in[5];
    const float* Wih_e = (const float*)d_in[6];
    const float* Whh_e = (const float*)d_in[7];
    const float* bih_e = (const float*)d_in[8];
    const float* bhh_e = (const float*)d_in[9];
    const float* Wih_d = (const float*)d_in[10];
    const float* Whh_d = (const float*)d_in[11];
    const float* bih_d = (const float*)d_in[12];
    const float* bhh_d = (const float*)d_in[13];
    const float* W_emb = (const float*)d_in[14];
    const float* b_emb = (const float*)d_in[15];
    float* out = (float*)d_out;

    const int B = in_sizes[0] / 40;   // input_traj [B][20][2]

    // SMEM bytes: 2*G*KP*2 (W hi/lo) + 4*64*KP*2 (h hi/lo x 2 buf)
    // cent: H=32, KCE=3, KP=56 ->  2*128*56*2 + 4*64*56*2 =  57,344
    // enc : H=64, KCE=5, KP=88 ->  2*256*88*2 + 4*64*88*2 = 135,168
    const int smc_b = 2*128*56*2 + 4*64*56*2;
    const int sme_b = 2*256*88*2 + 4*64*88*2;

    cudaFuncSetAttribute(lstm_rec_mma<32,100,64,2>, cudaFuncAttributeMaxDynamicSharedMemorySize, smc_b);
    cudaFuncSetAttribute(lstm_rec_mma<64, 20, 0,1>, cudaFuncAttributeMaxDynamicSharedMemorySize, sme_b);
    cudaFuncSetAttribute(lstm_dec_mma, cudaFuncAttributeMaxDynamicSharedMemorySize, SM_TOT);

    // centerline LSTM (H=32, T=100) -> g_h0/g_c0[.., 64..95]  (2 CTAs/SM)
    lstm_rec_mma<32,100,64,2><<<B / 64, 512, smc_b>>>(cent, Wih_c, Whh_c, bih_c, bhh_c);
    // encoder LSTM (H=64, T=20)    -> g_h0/g_c0[.., 0..63]
    lstm_rec_mma<64, 20, 0,1><<<B / 64, 512, sme_b>>>(traj, Wih_e, Whh_e, bih_e, bhh_e);
    // decoder on HMMA fp16 2-pass (H=96, 30 steps, 64 elems/CTA) -> out [B][30][2]
    lstm_dec_mma<<<B / 64, DNT, SM_TOT>>>(Wih_d, Whh_d, bih_d, bhh_d, W_emb, b_emb, out);
}

// round 15
// speedup vs baseline: 1.0932x; 1.0932x over previous
#include <cuda_runtime.h>
#include <cuda_fp16.h>

typedef unsigned long long u64;
typedef unsigned int u32;
#define BATCH 131072

// inter-phase state: concat layout [b][96], enc at 0..63, cent at 64..95
__device__ float g_h0[(size_t)BATCH * 96];
__device__ float g_c0[(size_t)BATCH * 96];

__device__ __forceinline__ float ex2f(float x){ float y; asm("ex2.approx.f32 %0, %1;" : "=f"(y) : "f"(x)); return y; }
__device__ __forceinline__ float rcpf(float x){ float y; asm("rcp.approx.f32 %0, %1;" : "=f"(y) : "f"(x)); return y; }
__device__ __forceinline__ float sigmf(float x){ return rcpf(1.0f + ex2f(-1.4426950408889634f * x)); }
__device__ __forceinline__ float tanhf_(float x){ return 1.0f - 2.0f * rcpf(1.0f + ex2f(2.8853900817779268f * x)); }

__device__ __forceinline__ void ffma2(u64 &d, u64 a, u64 b){
    asm("fma.rn.f32x2 %0, %1, %2, %0;" : "+l"(d) : "l"(a), "l"(b));
}
__device__ __forceinline__ float red2(u64 a){
    float lo, hi; asm("mov.b64 {%0, %1}, %2;" : "=f"(lo), "=f"(hi) : "l"(a)); return lo + hi;
}
__device__ __forceinline__ u64 pk2(float x, float y){
    u64 r; asm("mov.b64 %0, {%1, %2};" : "=l"(r) : "f"(x), "f"(y)); return r;
}
__device__ __forceinline__ u32 smem_u32(const void* p){
    u32 a; asm("{ .reg .u64 t; cvta.to.shared.u64 t, %1; cvt.u32.u64 %0, t; }" : "=r"(a) : "l"(p)); return a;
}
__device__ __forceinline__ void ldsm4(u32 &r0, u32 &r1, u32 &r2, u32 &r3, u32 addr){
    asm volatile("ldmatrix.sync.aligned.m8n8.x4.shared.b16 {%0,%1,%2,%3}, [%4];"
        : "=r"(r0), "=r"(r1), "=r"(r2), "=r"(r3) : "r"(addr));
}
__device__ __forceinline__ void mma_f16(float &d0, float &d1, float &d2, float &d3,
                                        const u32* a, u32 b0, u32 b1){
    asm volatile("mma.sync.aligned.m16n8k16.row.col.f32.f16.f16.f32 "
        "{%0,%1,%2,%3}, {%4,%5,%6,%7}, {%8,%9}, {%0,%1,%2,%3};"
        : "+f"(d0), "+f"(d1), "+f"(d2), "+f"(d3)
        : "r"(a[0]), "r"(a[1]), "r"(a[2]), "r"(a[3]), "r"(b0), "r"(b1));
}

// ---------------------------------------------------------------------------
// cent / enc recurrent phase on HMMA, 2-pass (W quantized fp16, h split
// hi/lo — decoder-proven precision scheme). x-projection AND bias folded
// into the MMA contraction: h_ext = [h; x0; x1; 1].
// Both-lane epilogue, double-buffered h, one barrier per step.
// ---------------------------------------------------------------------------
template<int H, int T, int OFF, int MINB>
__global__ __launch_bounds__(512, MINB)
void lstm_rec_mma(const float* __restrict__ x_g,
                  const float* __restrict__ Wih, const float* __restrict__ Whh,
                  const float* __restrict__ bih, const float* __restrict__ bhh)
{
    constexpr int G     = 4 * H;
    constexpr int NE    = 64;
    constexpr int KCE   = (H + 3 + 15) / 16;  // k16 chunks incl x(2)+bias(1)
    constexpr int KP    = KCE * 16 + 8;       // halves per row
    constexpr int WROWB = 2 * KP;             // bytes per row
    constexpr int NPAIR = H / 16;             // n8-tile pairs per warp
    constexpr int HBUF  = NE * WROWB;         // one h buffer, bytes
    // SMEM byte offsets (W hi only)
    constexpr int SWHI = 0;
    constexpr int SHHI = SWHI + G * KP * 2;   // 2 buffers
    constexpr int SHLO = SHHI + 2 * HBUF;     // 2 buffers

    extern __shared__ char smc[];
    const u32 smb = smem_u32(smc);

    const int tid = threadIdx.x;
    const size_t b0 = (size_t)blockIdx.x * NE;

    // ---- W_ext fill: torch row = g*H+j -> interleaved col r = 4j+g, fp16 ----
    for (int i = tid; i < G * KP; i += 512){
        int r = i / KP, k = i % KP;
        int j = r >> 2, g = r & 3;
        int trow = g * H + j;
        float w;
        if (k < H)            w = Whh[trow * H + k];
        else if (k == H)      w = Wih[trow * 2];
        else if (k == H + 1)  w = Wih[trow * 2 + 1];
        else if (k == H + 2)  w = bih[trow] + bhh[trow];
        else                  w = 0.0f;
        *(__half*)(smc + SWHI + i * 2) = __float2half_rn(w);
    }
    // h buffers: zero everything (both buffers, hi+lo)
    for (int i = tid; i < 2 * NE * KP; i += 512){
        *(__half*)(smc + SHHI + i * 2) = __float2half_rn(0.f);
        *(__half*)(smc + SHLO + i * 2) = __float2half_rn(0.f);
    }
    __syncthreads();
    // const-1 slot (both buffers) + x(t=0) into buffer 0
    if (tid < NE){
        const int e = tid;
        *(__half*)(smc + SHHI + (e * KP + H + 2) * 2) = __float2half_rn(1.0f);
        *(__half*)(smc + SHHI + HBUF + (e * KP + H + 2) * 2) = __float2half_rn(1.0f);
        float2 xv = *(const float2*)(x_g + (b0 + e) * (size_t)(2 * T));
        __half h0 = __float2half_rn(xv.x), h1 = __float2half_rn(xv.y);
        *(__half2*)(smc + SHHI + (e * KP + H) * 2) = __halves2half2(h0, h1);
        *(__half2*)(smc + SHLO + (e * KP + H) * 2) =
            __halves2half2(__float2half_rn(xv.x - __half2float(h0)),
                           __float2half_rn(xv.y - __half2float(h1)));
    }

    const int wid = tid >> 5, lane = tid & 31;
    const int cg = wid & 3, rg = wid >> 2;
    const int e0 = rg * 16, colbase = cg * H;
    const int tg = lane & 3, gq = lane >> 2;
    const bool is_even = (tg & 1) == 0;
    const int el = e0 + gq + (is_even ? 0 : 8);   // this lane's element
    const bool xw = (cg == 0 && tg < 2);          // x-writer lane

    // ldmatrix per-lane addresses (buffer 0 bases)
    const int a_row = e0 + (lane & 7) + ((lane >> 3) & 1) * 8;
    const u32 a_koff = ((lane >> 4) & 1) * 16;
    const u32 ah_base = smb + SHHI + (u32)a_row * WROWB + a_koff;
    const u32 al_base = smb + SHLO + (u32)a_row * WROWB + a_koff;
    const int b4_row = colbase + ((lane >> 4) << 3) + (lane & 7);
    const u32 b4_koff = ((lane >> 3) & 1) * 16;
    const u32 bh4_base = smb + SWHI + (u32)b4_row * WROWB + b4_koff;

    constexpr int NCELL = H / 8;
    float c[NCELL];
    #pragma unroll
    for (int n0 = 0; n0 < NCELL; n0++) c[n0] = 0.f;

    __syncthreads();

    for (int t = 0; t < T; t++){
        const u32 roff = (u32)(t & 1) * HBUF;        // read buffer
        const u32 woff = (u32)((t + 1) & 1) * HBUF;  // write buffer

        // prefetch next step's x (designated lanes only)
        float2 xn = make_float2(0.f, 0.f);
        if (xw && t + 1 < T)
            xn = *(const float2*)(x_g + (b0 + el) * (size_t)(2 * T) + 2 * (t + 1));

        // A fragments (h_ext hi/lo) from read buffer
        u32 ahi[KCE][4], alo[KCE][4];
        #pragma unroll
        for (int kc = 0; kc < KCE; kc++){
            ldsm4(ahi[kc][0], ahi[kc][1], ahi[kc][2], ahi[kc][3], ah_base + roff + kc * 32);
            ldsm4(alo[kc][0], alo[kc][1], alo[kc][2], alo[kc][3], al_base + roff + kc * 32);
        }

        #pragma unroll
        for (int p = 0; p < NPAIR; p++){
            float d[2][4];
            #pragma unroll
            for (int h2 = 0; h2 < 2; h2++)
                #pragma unroll
                for (int r2 = 0; r2 < 4; r2++) d[h2][r2] = 0.f;
            const u32 bhp = bh4_base + (u32)(p * 16) * WROWB;
            #pragma unroll
            for (int kc = 0; kc < KCE; kc++){
                u32 bq0, bq1, bq2, bq3;
                ldsm4(bq0, bq1, bq2, bq3, bhp + kc * 32);
                mma_f16(d[0][0], d[0][1], d[0][2], d[0][3], ahi[kc], bq0, bq1);
                mma_f16(d[0][0], d[0][1], d[0][2], d[0][3], alo[kc], bq0, bq1);
                mma_f16(d[1][0], d[1][1], d[1][2], d[1][3], ahi[kc], bq2, bq3);
                mma_f16(d[1][0], d[1][1], d[1][2], d[1][3], alo[kc], bq2, bq3);
            }
            #pragma unroll
            for (int h2 = 0; h2 < 2; h2++){
                const int n0 = 2 * p + h2;
                float d0 = d[h2][0], d1 = d[h2][1], d2 = d[h2][2], d3 = d[h2][3];
                // parity-select exchange: even lane -> eA's 4 gates, odd -> eB's
                float ra = __shfl_xor_sync(0xffffffffu, is_even ? d2 : d0, 1);
                float rb = __shfl_xor_sync(0xffffffffu, is_even ? d3 : d1, 1);
                float gi = is_even ? d0 : ra;
                float gf = is_even ? d1 : rb;
                float gg = is_even ? ra : d2;
                float go = is_even ? rb : d3;
                const int r4 = colbase + n0 * 8 + (tg >> 1) * 4;   // = 4j
                const int j = r4 >> 2;
                float cn = sigmf(gf) * c[n0] + sigmf(gi) * tanhf_(gg);
                float hv = sigmf(go) * tanhf_(cn);
                c[n0] = cn;
                __half hh = __float2half_rn(hv);
                *(__half*)(smc + SHHI + woff + (el * KP + j) * 2) = hh;
                *(__half*)(smc + SHLO + woff + (el * KP + j) * 2) = __float2half_rn(hv - __half2float(hh));
                if (t == T - 1){
                    g_h0[(b0 + el) * 96 + OFF + j] = hv;
                    g_c0[(b0 + el) * 96 + OFF + j] = cn;
                }
            }
        }
        // write x_{t+1} into the write buffer (designated lanes)
        if (xw && t + 1 < T){
            __half h0 = __float2half_rn(xn.x), h1 = __float2half_rn(xn.y);
            *(__half2*)(smc + SHHI + woff + (el * KP + H) * 2) = __halves2half2(h0, h1);
            *(__half2*)(smc + SHLO + woff + (el * KP + H) * 2) =
                __halves2half2(__float2half_rn(xn.x - __half2float(h0)),
                               __float2half_rn(xn.y - __half2float(h1)));
        }
        __syncthreads();   // single barrier per step
    }
}

// ---------------------------------------------------------------------------
// decoder on HMMA, fp16 2-pass, NE=64 elems/CTA, both-lane epilogue,
// double-buffered h (one barrier per step). Unchanged (passing since R12).
// ---------------------------------------------------------------------------
#define DNT 512
#define SW_HI   0          // W_hi  [384][104] fp16          (79,872)
#define SH_HI   79872      // h_hi  2 x [64][104] fp16       (26,624)
#define SH_LO   106496     // h_lo  2 x [64][104] fp16       (26,624)
#define S_BSD   133120     // bias  [384] f32                (1,536)
#define S_WEX   134656     // [96] f32
#define S_WEY   135040     // [96] f32
#define SM_TOT  135424
#define WROW    208
#define DHBUF   (64 * WROW)   // 13,312 bytes per h buffer

__global__ __launch_bounds__(DNT, 1)
void lstm_dec_mma(const float* __restrict__ Wih, const float* __restrict__ Whh,
                  const float* __restrict__ bih, const float* __restrict__ bhh,
                  const float* __restrict__ Wemb, const float* __restrict__ bemb,
                  float* __restrict__ out)
{
    extern __shared__ char smc[];
    float* bsd  = (float*)(smc + S_BSD);
    float* wex  = (float*)(smc + S_WEX);
    float* wey  = (float*)(smc + S_WEY);
    const u32 smb = smem_u32(smc);

    const int tid = threadIdx.x;
    const size_t b0 = (size_t)blockIdx.x * 64;

    for (int i = tid; i < 384 * 96; i += DNT){
        int trow = i / 96, k = i % 96;
        int g = trow / 96, j = trow % 96;
        float w = Wih[i] + Whh[i];
        int r = 4 * j + g;
        *(__half*)(smc + SW_HI + (r * 104 + k) * 2) = __float2half_rn(w);
    }
    for (int i = tid; i < 384; i += DNT){
        int g = i / 96, j = i % 96;
        bsd[4 * j + g] = bih[i] + bhh[i];
    }
    for (int i = tid; i < 96; i += DNT){ wex[i] = Wemb[i]; wey[i] = Wemb[96 + i]; }

    // h0 into buffer 0
    for (int i = tid; i < 64 * 96; i += DNT){
        int e = i / 96, j = i % 96;
        float v = g_h0[(b0 + e) * 96 + j];
        __half hi = __float2half_rn(v);
        __half lo = __float2half_rn(v - __half2float(hi));
        *(__half*)(smc + SH_HI + (e * 104 + j) * 2) = hi;
        *(__half*)(smc + SH_LO + (e * 104 + j) * 2) = lo;
    }

    const int wid = tid >> 5, lane = tid & 31;
    const int cg = wid & 3, rg = wid >> 2;
    const int e0 = rg * 16, colbase = cg * 96;
    const int tg = lane & 3, gq = lane >> 2;
    const bool is_even = (tg & 1) == 0;
    const int el = e0 + gq + (is_even ? 0 : 8);

    const int a_row = e0 + (lane & 7) + ((lane >> 3) & 1) * 8;
    const u32 a_koff = ((lane >> 4) & 1) * 16;
    const u32 ah_base = smb + SH_HI + (u32)a_row * WROW + a_koff;
    const u32 al_base = smb + SH_LO + (u32)a_row * WROW + a_koff;
    const int b4_row = colbase + ((lane >> 4) << 3) + (lane & 7);
    const u32 b4_koff = ((lane >> 3) & 1) * 16;
    const u32 b4_base = smb + SW_HI + (u32)b4_row * WROW + b4_koff;

    float c[12];
    #pragma unroll
    for (int n0 = 0; n0 < 12; n0++){
        int j = cg * 24 + 2 * n0 + (tg >> 1);
        c[n0] = g_c0[(b0 + el) * 96 + j];
    }
    const float bex = bemb[0], bey = bemb[1];
    __syncthreads();

    for (int t = 0; t < 30; t++){
        const u32 roff = (u32)(t & 1) * DHBUF;
        const u32 woff = (u32)((t + 1) & 1) * DHBUF;

        u32 ahi[6][4], alo[6][4];
        #pragma unroll
        for (int kc = 0; kc < 6; kc++){
            ldsm4(ahi[kc][0], ahi[kc][1], ahi[kc][2], ahi[kc][3], ah_base + roff + kc * 32);
            ldsm4(alo[kc][0], alo[kc][1], alo[kc][2], alo[kc][3], al_base + roff + kc * 32);
        }

        #pragma unroll
        for (int p = 0; p < 6; p++){
            float d[2][4];
            #pragma unroll
            for (int h2 = 0; h2 < 2; h2++)
                #pragma unroll
                for (int r2 = 0; r2 < 4; r2++) d[h2][r2] = 0.f;
            const u32 bp = b4_base + (u32)(p * 16) * WROW;
            #pragma unroll
            for (int kc = 0; kc < 6; kc++){
                u32 bq0, bq1, bq2, bq3;
                ldsm4(bq0, bq1, bq2, bq3, bp + kc * 32);
                mma_f16(d[0][0], d[0][1], d[0][2], d[0][3], ahi[kc], bq0, bq1);
                mma_f16(d[0][0], d[0][1], d[0][2], d[0][3], alo[kc], bq0, bq1);
                mma_f16(d[1][0], d[1][1], d[1][2], d[1][3], ahi[kc], bq2, bq3);
                mma_f16(d[1][0], d[1][1], d[1][2], d[1][3], alo[kc], bq2, bq3);
            }
            #pragma unroll
            for (int h2 = 0; h2 < 2; h2++){
                const int n0 = 2 * p + h2;
                float d0 = d[h2][0], d1 = d[h2][1], d2 = d[h2][2], d3 = d[h2][3];
                float ra = __shfl_xor_sync(0xffffffffu, is_even ? d2 : d0, 1);
                float rb = __shfl_xor_sync(0xffffffffu, is_even ? d3 : d1, 1);
                float gi_ = is_even ? d0 : ra;
                float gf_ = is_even ? d1 : rb;
                float gg_ = is_even ? ra : d2;
                float go_ = is_even ? rb : d3;
                const int r4 = colbase + n0 * 8 + (tg >> 1) * 4;
                const int j = r4 >> 2;
                float cn = sigmf(gf_ + bsd[r4+1]) * c[n0] + sigmf(gi_ + bsd[r4]) * tanhf_(gg_ + bsd[r4+2]);
                float hv = sigmf(go_ + bsd[r4+3]) * tanhf_(cn);
                c[n0] = cn;
                __half hh = __float2half_rn(hv);
                *(__half*)(smc + SH_HI + woff + (el * 104 + j) * 2) = hh;
                *(__half*)(smc + SH_LO + woff + (el * 104 + j) * 2) = __float2half_rn(hv - __half2float(hh));
            }
        }
        __syncthreads();   // single barrier: h_t visible for pos + next step

        if (tid < 64){
            u64 ax = 0ULL, ay = 0ULL;
            const __half2* ph = (const __half2*)(smc + SH_HI + woff + tid * WROW);
            const __half2* pl = (const __half2*)(smc + SH_LO + woff + tid * WROW);
            #pragma unroll 8
            for (int kk = 0; kk < 48; kk++){
                float2 hi = __half22float2(ph[kk]);
                float2 lo = __half22float2(pl[kk]);
                u64 hd = pk2(hi.x + lo.x, hi.y + lo.y);
                ffma2(ax, hd, *(const u64*)&wex[2 * kk]);
                ffma2(ay, hd, *(const u64*)&wey[2 * kk]);
            }
            float2 o; o.x = red2(ax) + bex; o.y = red2(ay) + bey;
            *(float2*)(out + (b0 + tid) * 60 + 2 * t) = o;
        }
    }
}

extern "C" void kernel_launch(void* const* d_in, const int* in_sizes, int n_in,
                              void* d_out, int out_size)
{
    (void)n_in; (void)out_size;
    const float* traj  = (const float*)d_in[0];
    const float* cent  = (const float*)d_in[1];
    const float* Wih_c = (const float*)d_in[2];
    const float* Whh_c = (const float*)d_in[3];
    const float* bih_c = (const float*)d_in[4];
    const float* bhh_c = (const float*)d_in[5];
    const float* Wih_e = (const float*)d_in[6];
    const float* Whh_e = (const float*)d_in[7];
    const float* bih_e = (const float*)d_in[8];
    const float* bhh_e = (const float*)d_in[9];
    const float* Wih_d = (const float*)d_in[10];
    const float* Whh_d = (const float*)d_in[11];
    const float* bih_d = (const float*)d_in[12];
    const float* bhh_d = (const float*)d_in[13];
    const float* W_emb = (const float*)d_in[14];
    const float* b_emb = (const float*)d_in[15];
    float* out = (float*)d_out;

    const int B = in_sizes[0] / 40;   // input_traj [B][20][2]

    // SMEM bytes: G*KP*2 (W hi only) + 4*64*KP*2 (h hi/lo x 2 buf)
    // cent: H=32, KCE=3, KP=56 ->  128*56*2 + 4*64*56*2 =  43,008
    // enc : H=64, KCE=5, KP=88 ->  256*88*2 + 4*64*88*2 =  90,112
    const int smc_b = 128*56*2 + 4*64*56*2;
    const int sme_b = 256*88*2 + 4*64*88*2;

    cudaFuncSetAttribute(lstm_rec_mma<32,100,64,2>, cudaFuncAttributeMaxDynamicSharedMemorySize, smc_b);
    cudaFuncSetAttribute(lstm_rec_mma<64, 20, 0,1>, cudaFuncAttributeMaxDynamicSharedMemorySize, sme_b);
    cudaFuncSetAttribute(lstm_dec_mma, cudaFuncAttributeMaxDynamicSharedMemorySize, SM_TOT);

    // centerline LSTM (H=32, T=100) -> g_h0/g_c0[.., 64..95]  (2 CTAs/SM)
    lstm_rec_mma<32,100,64,2><<<B / 64, 512, smc_b>>>(cent, Wih_c, Whh_c, bih_c, bhh_c);
    // encoder LSTM (H=64, T=20)    -> g_h0/g_c0[.., 0..63]
    lstm_rec_mma<64, 20, 0,1><<<B / 64, 512, sme_b>>>(traj, Wih_e, Whh_e, bih_e, bhh_e);
    // decoder on HMMA fp16 2-pass (H=96, 30 steps, 64 elems/CTA) -> out [B][30][2]
    lstm_dec_mma<<<B / 64, DNT, SM_TOT>>>(Wih_d, Whh_d, bih_d, bhh_d, W_emb, b_emb, out);
}

// round 16
// speedup vs baseline: 1.1793x; 1.0788x over previous
#include <cuda_runtime.h>
#include <cuda_fp16.h>

typedef unsigned long long u64;
typedef unsigned int u32;
#define BATCH 131072

// inter-phase state: concat layout [b][96], enc at 0..63, cent at 64..95
__device__ float g_h0[(size_t)BATCH * 96];
__device__ float g_c0[(size_t)BATCH * 96];

__device__ __forceinline__ float ex2f(float x){ float y; asm("ex2.approx.f32 %0, %1;" : "=f"(y) : "f"(x)); return y; }
__device__ __forceinline__ float rcpf(float x){ float y; asm("rcp.approx.f32 %0, %1;" : "=f"(y) : "f"(x)); return y; }
__device__ __forceinline__ float sigmf(float x){ return rcpf(1.0f + ex2f(-1.4426950408889634f * x)); }
__device__ __forceinline__ float tanhf_(float x){ return 1.0f - 2.0f * rcpf(1.0f + ex2f(2.8853900817779268f * x)); }

__device__ __forceinline__ void ffma2(u64 &d, u64 a, u64 b){
    asm("fma.rn.f32x2 %0, %1, %2, %0;" : "+l"(d) : "l"(a), "l"(b));
}
__device__ __forceinline__ float red2(u64 a){
    float lo, hi; asm("mov.b64 {%0, %1}, %2;" : "=f"(lo), "=f"(hi) : "l"(a)); return lo + hi;
}
__device__ __forceinline__ u64 pk2(float x, float y){
    u64 r; asm("mov.b64 %0, {%1, %2};" : "=l"(r) : "f"(x), "f"(y)); return r;
}
__device__ __forceinline__ u32 smem_u32(const void* p){
    u32 a; asm("{ .reg .u64 t; cvta.to.shared.u64 t, %1; cvt.u32.u64 %0, t; }" : "=r"(a) : "l"(p)); return a;
}
__device__ __forceinline__ void ldsm4(u32 &r0, u32 &r1, u32 &r2, u32 &r3, u32 addr){
    asm volatile("ldmatrix.sync.aligned.m8n8.x4.shared.b16 {%0,%1,%2,%3}, [%4];"
        : "=r"(r0), "=r"(r1), "=r"(r2), "=r"(r3) : "r"(addr));
}
__device__ __forceinline__ void mma_f16(float &d0, float &d1, float &d2, float &d3,
                                        const u32* a, u32 b0, u32 b1){
    asm volatile("mma.sync.aligned.m16n8k16.row.col.f32.f16.f16.f32 "
        "{%0,%1,%2,%3}, {%4,%5,%6,%7}, {%8,%9}, {%0,%1,%2,%3};"
        : "+f"(d0), "+f"(d1), "+f"(d2), "+f"(d3)
        : "r"(a[0]), "r"(a[1]), "r"(a[2]), "r"(a[3]), "r"(b0), "r"(b1));
}

// ---------------------------------------------------------------------------
// cent / enc recurrent phase on HMMA, 2-pass (W fp16, h split hi/lo).
// x-projection + bias folded into contraction (h_ext = [h; x0; x1; 1]).
// IF/GO split column layout: (i,f) of unit j at cols {2j,2j+1} in [0,2H);
// (g,o) at {2j,2j+1} in [2H,4H). Each lane gets all 4 gates of its units
// for rows eA/eB directly from two D fragments -> NO shfl, NO selects.
// Double-buffered h, one barrier per step.
// ---------------------------------------------------------------------------
template<int H, int T, int OFF, int MINB>
__global__ __launch_bounds__(512, MINB)
void lstm_rec_mma(const float* __restrict__ x_g,
                  const float* __restrict__ Wih, const float* __restrict__ Whh,
                  const float* __restrict__ bih, const float* __restrict__ bhh)
{
    constexpr int G     = 4 * H;
    constexpr int NE    = 64;
    constexpr int KCE   = (H + 3 + 15) / 16;  // k16 chunks incl x(2)+bias(1)
    constexpr int KP    = KCE * 16 + 8;       // halves per row
    constexpr int WROWB = 2 * KP;             // bytes per row
    constexpr int NP2   = H / 32;             // n8-tile pairs per region per warp
    constexpr int HBUF  = NE * WROWB;         // one h buffer, bytes
    constexpr int SWHI = 0;
    constexpr int SHHI = SWHI + G * KP * 2;   // 2 buffers
    constexpr int SHLO = SHHI + 2 * HBUF;     // 2 buffers

    extern __shared__ char smc[];
    const u32 smb = smem_u32(smc);

    const int tid = threadIdx.x;
    const size_t b0 = (size_t)blockIdx.x * NE;

    // ---- W_ext fill: torch row = g*H+j -> IF/GO interleaved col ----
    for (int i = tid; i < G * KP; i += 512){
        int r = i / KP, k = i % KP;
        // invert col map: r < 2H: unit j = r>>1, gate = r&1 (i/f)
        //                 r >= 2H: unit j = (r-2H)>>1, gate = 2 + ((r-2H)&1)
        int j, g;
        if (r < 2 * H){ j = r >> 1; g = r & 1; }
        else          { j = (r - 2 * H) >> 1; g = 2 + ((r - 2 * H) & 1); }
        int trow = g * H + j;
        float w;
        if (k < H)            w = Whh[trow * H + k];
        else if (k == H)      w = Wih[trow * 2];
        else if (k == H + 1)  w = Wih[trow * 2 + 1];
        else if (k == H + 2)  w = bih[trow] + bhh[trow];
        else                  w = 0.0f;
        *(__half*)(smc + SWHI + i * 2) = __float2half_rn(w);
    }
    for (int i = tid; i < 2 * NE * KP; i += 512){
        *(__half*)(smc + SHHI + i * 2) = __float2half_rn(0.f);
        *(__half*)(smc + SHLO + i * 2) = __float2half_rn(0.f);
    }
    __syncthreads();
    if (tid < NE){
        const int e = tid;
        *(__half*)(smc + SHHI + (e * KP + H + 2) * 2) = __float2half_rn(1.0f);
        *(__half*)(smc + SHHI + HBUF + (e * KP + H + 2) * 2) = __float2half_rn(1.0f);
        float2 xv = *(const float2*)(x_g + (b0 + e) * (size_t)(2 * T));
        __half h0 = __float2half_rn(xv.x), h1 = __float2half_rn(xv.y);
        *(__half2*)(smc + SHHI + (e * KP + H) * 2) = __halves2half2(h0, h1);
        *(__half2*)(smc + SHLO + (e * KP + H) * 2) =
            __halves2half2(__float2half_rn(xv.x - __half2float(h0)),
                           __float2half_rn(xv.y - __half2float(h1)));
    }

    const int wid = tid >> 5, lane = tid & 31;
    const int cg = wid & 3, rg = wid >> 2;
    const int e0 = rg * 16;
    const int tg = lane & 3, gq = lane >> 2;
    const int eA = e0 + gq, eB = eA + 8;
    const bool xw = (cg == 0 && tg == 0);   // x-writer lane (covers eA and eB)

    // ldmatrix per-lane addresses
    const int a_row = e0 + (lane & 7) + ((lane >> 3) & 1) * 8;
    const u32 a_koff = ((lane >> 4) & 1) * 16;
    const u32 ah_base = smb + SHHI + (u32)a_row * WROWB + a_koff;
    const u32 al_base = smb + SHLO + (u32)a_row * WROWB + a_koff;
    const int b_sub = ((lane >> 4) << 3) + (lane & 7);
    const u32 b4_koff = ((lane >> 3) & 1) * 16;
    const u32 bIF_base = smb + SWHI + (u32)(cg * (H / 2) + b_sub) * WROWB + b4_koff;
    const u32 bGO_base = smb + SWHI + (u32)(2 * H + cg * (H / 2) + b_sub) * WROWB + b4_koff;

    constexpr int NCELL = H / 8;
    float c[NCELL];
    #pragma unroll
    for (int n0 = 0; n0 < NCELL; n0++) c[n0] = 0.f;

    __syncthreads();

    for (int t = 0; t < T; t++){
        const u32 roff = (u32)(t & 1) * HBUF;
        const u32 woff = (u32)((t + 1) & 1) * HBUF;

        float2 xnA = make_float2(0.f, 0.f), xnB = make_float2(0.f, 0.f);
        if (xw && t + 1 < T){
            xnA = *(const float2*)(x_g + (b0 + eA) * (size_t)(2 * T) + 2 * (t + 1));
            xnB = *(const float2*)(x_g + (b0 + eB) * (size_t)(2 * T) + 2 * (t + 1));
        }

        u32 ahi[KCE][4], alo[KCE][4];
        #pragma unroll
        for (int kc = 0; kc < KCE; kc++){
            ldsm4(ahi[kc][0], ahi[kc][1], ahi[kc][2], ahi[kc][3], ah_base + roff + kc * 32);
            ldsm4(alo[kc][0], alo[kc][1], alo[kc][2], alo[kc][3], al_base + roff + kc * 32);
        }

        #pragma unroll
        for (int p = 0; p < NP2; p++){
            float dIF[2][4], dGO[2][4];
            #pragma unroll
            for (int h2 = 0; h2 < 2; h2++)
                #pragma unroll
                for (int r2 = 0; r2 < 4; r2++){ dIF[h2][r2] = 0.f; dGO[h2][r2] = 0.f; }
            const u32 bifp = bIF_base + (u32)(p * 16) * WROWB;
            const u32 bgop = bGO_base + (u32)(p * 16) * WROWB;
            #pragma unroll
            for (int kc = 0; kc < KCE; kc++){
                u32 f0, f1, f2, f3, g0, g1, g2, g3;
                ldsm4(f0, f1, f2, f3, bifp + kc * 32);
                ldsm4(g0, g1, g2, g3, bgop + kc * 32);
                mma_f16(dIF[0][0], dIF[0][1], dIF[0][2], dIF[0][3], ahi[kc], f0, f1);
                mma_f16(dIF[0][0], dIF[0][1], dIF[0][2], dIF[0][3], alo[kc], f0, f1);
                mma_f16(dIF[1][0], dIF[1][1], dIF[1][2], dIF[1][3], ahi[kc], f2, f3);
                mma_f16(dIF[1][0], dIF[1][1], dIF[1][2], dIF[1][3], alo[kc], f2, f3);
                mma_f16(dGO[0][0], dGO[0][1], dGO[0][2], dGO[0][3], ahi[kc], g0, g1);
                mma_f16(dGO[0][0], dGO[0][1], dGO[0][2], dGO[0][3], alo[kc], g0, g1);
                mma_f16(dGO[1][0], dGO[1][1], dGO[1][2], dGO[1][3], ahi[kc], g2, g3);
                mma_f16(dGO[1][0], dGO[1][1], dGO[1][2], dGO[1][3], alo[kc], g2, g3);
            }
            #pragma unroll
            for (int h2 = 0; h2 < 2; h2++){
                const int n0 = 2 * p + h2;
                const int j = cg * (H / 4) + n0 * 4 + tg;
                // elem A: gates (i,f) = dIF[h2][0..1], (g,o) = dGO[h2][0..1]
                float cnA = sigmf(dIF[h2][1]) * c[2 * n0] + sigmf(dIF[h2][0]) * tanhf_(dGO[h2][0]);
                float hA  = sigmf(dGO[h2][1]) * tanhf_(cnA);
                c[2 * n0] = cnA;
                // elem B: rows +8
                float cnB = sigmf(dIF[h2][3]) * c[2 * n0 + 1] + sigmf(dIF[h2][2]) * tanhf_(dGO[h2][2]);
                float hB  = sigmf(dGO[h2][3]) * tanhf_(cnB);
                c[2 * n0 + 1] = cnB;
                __half hAh = __float2half_rn(hA);
                __half hBh = __float2half_rn(hB);
                *(__half*)(smc + SHHI + woff + (eA * KP + j) * 2) = hAh;
                *(__half*)(smc + SHHI + woff + (eB * KP + j) * 2) = hBh;
                *(__half*)(smc + SHLO + woff + (eA * KP + j) * 2) = __float2half_rn(hA - __half2float(hAh));
                *(__half*)(smc + SHLO + woff + (eB * KP + j) * 2) = __float2half_rn(hB - __half2float(hBh));
                if (t == T - 1){
                    g_h0[(b0 + eA) * 96 + OFF + j] = hA;
                    g_h0[(b0 + eB) * 96 + OFF + j] = hB;
                    g_c0[(b0 + eA) * 96 + OFF + j] = cnA;
                    g_c0[(b0 + eB) * 96 + OFF + j] = cnB;
                }
            }
        }
        if (xw && t + 1 < T){
            __half a0 = __float2half_rn(xnA.x), a1 = __float2half_rn(xnA.y);
            __half b0h = __float2half_rn(xnB.x), b1h = __float2half_rn(xnB.y);
            *(__half2*)(smc + SHHI + woff + (eA * KP + H) * 2) = __halves2half2(a0, a1);
            *(__half2*)(smc + SHLO + woff + (eA * KP + H) * 2) =
                __halves2half2(__float2half_rn(xnA.x - __half2float(a0)),
                               __float2half_rn(xnA.y - __half2float(a1)));
            *(__half2*)(smc + SHHI + woff + (eB * KP + H) * 2) = __halves2half2(b0h, b1h);
            *(__half2*)(smc + SHLO + woff + (eB * KP + H) * 2) =
                __halves2half2(__float2half_rn(xnB.x - __half2float(b0h)),
                               __float2half_rn(xnB.y - __half2float(b1h)));
        }
        __syncthreads();   // single barrier per step
    }
}

// ---------------------------------------------------------------------------
// decoder on HMMA, fp16 2-pass, NE=64, IF/GO split layout (no shfl),
// double-buffered h, one barrier per step.
// ---------------------------------------------------------------------------
#define DNT 512
#define SW_HI   0          // W_hi  [384][104] fp16          (79,872)
#define SH_HI   79872      // h_hi  2 x [64][104] fp16       (26,624)
#define SH_LO   106496     // h_lo  2 x [64][104] fp16       (26,624)
#define S_BSD   133120     // bias  [384] f32 (IF/GO col layout)
#define S_WEX   134656     // [96] f32
#define S_WEY   135040     // [96] f32
#define SM_TOT  135424
#define WROW    208
#define DHBUF   (64 * WROW)   // 13,312 bytes per h buffer

__global__ __launch_bounds__(DNT, 1)
void lstm_dec_mma(const float* __restrict__ Wih, const float* __restrict__ Whh,
                  const float* __restrict__ bih, const float* __restrict__ bhh,
                  const float* __restrict__ Wemb, const float* __restrict__ bemb,
                  float* __restrict__ out)
{
    extern __shared__ char smc[];
    float* bsd  = (float*)(smc + S_BSD);
    float* wex  = (float*)(smc + S_WEX);
    float* wey  = (float*)(smc + S_WEY);
    const u32 smb = smem_u32(smc);

    const int tid = threadIdx.x;
    const size_t b0 = (size_t)blockIdx.x * 64;

    // W fill: torch row = g*96+j -> IF col 2j+g (g<2) / GO col 192+2j+(g-2)
    for (int i = tid; i < 384 * 96; i += DNT){
        int trow = i / 96, k = i % 96;
        int g = trow / 96, j = trow % 96;
        float w = Wih[i] + Whh[i];
        int r = (g < 2) ? (2 * j + g) : (192 + 2 * j + (g - 2));
        *(__half*)(smc + SW_HI + (r * 104 + k) * 2) = __float2half_rn(w);
    }
    for (int i = tid; i < 384; i += DNT){
        int g = i / 96, j = i % 96;
        int r = (g < 2) ? (2 * j + g) : (192 + 2 * j + (g - 2));
        bsd[r] = bih[i] + bhh[i];
    }
    for (int i = tid; i < 96; i += DNT){ wex[i] = Wemb[i]; wey[i] = Wemb[96 + i]; }

    // h0 into buffer 0
    for (int i = tid; i < 64 * 96; i += DNT){
        int e = i / 96, j = i % 96;
        float v = g_h0[(b0 + e) * 96 + j];
        __half hi = __float2half_rn(v);
        __half lo = __float2half_rn(v - __half2float(hi));
        *(__half*)(smc + SH_HI + (e * 104 + j) * 2) = hi;
        *(__half*)(smc + SH_LO + (e * 104 + j) * 2) = lo;
    }

    const int wid = tid >> 5, lane = tid & 31;
    const int cg = wid & 3, rg = wid >> 2;
    const int e0 = rg * 16;
    const int tg = lane & 3, gq = lane >> 2;
    const int eA = e0 + gq, eB = eA + 8;

    const int a_row = e0 + (lane & 7) + ((lane >> 3) & 1) * 8;
    const u32 a_koff = ((lane >> 4) & 1) * 16;
    const u32 ah_base = smb + SH_HI + (u32)a_row * WROW + a_koff;
    const u32 al_base = smb + SH_LO + (u32)a_row * WROW + a_koff;
    const int b_sub = ((lane >> 4) << 3) + (lane & 7);
    const u32 b4_koff = ((lane >> 3) & 1) * 16;
    const u32 bIF_base = smb + SW_HI + (u32)(cg * 48 + b_sub) * WROW + b4_koff;
    const u32 bGO_base = smb + SW_HI + (u32)(192 + cg * 48 + b_sub) * WROW + b4_koff;

    float c[12];
    #pragma unroll
    for (int n0 = 0; n0 < 6; n0++){
        int j = cg * 24 + n0 * 4 + tg;
        c[2 * n0]     = g_c0[(b0 + eA) * 96 + j];
        c[2 * n0 + 1] = g_c0[(b0 + eB) * 96 + j];
    }
    const float bex = bemb[0], bey = bemb[1];
    __syncthreads();

    for (int t = 0; t < 30; t++){
        const u32 roff = (u32)(t & 1) * DHBUF;
        const u32 woff = (u32)((t + 1) & 1) * DHBUF;

        u32 ahi[6][4], alo[6][4];
        #pragma unroll
        for (int kc = 0; kc < 6; kc++){
            ldsm4(ahi[kc][0], ahi[kc][1], ahi[kc][2], ahi[kc][3], ah_base + roff + kc * 32);
            ldsm4(alo[kc][0], alo[kc][1], alo[kc][2], alo[kc][3], al_base + roff + kc * 32);
        }

        #pragma unroll
        for (int p = 0; p < 3; p++){
            float dIF[2][4], dGO[2][4];
            #pragma unroll
            for (int h2 = 0; h2 < 2; h2++)
                #pragma unroll
                for (int r2 = 0; r2 < 4; r2++){ dIF[h2][r2] = 0.f; dGO[h2][r2] = 0.f; }
            const u32 bifp = bIF_base + (u32)(p * 16) * WROW;
            const u32 bgop = bGO_base + (u32)(p * 16) * WROW;
            #pragma unroll
            for (int kc = 0; kc < 6; kc++){
                u32 f0, f1, f2, f3, g0, g1, g2, g3;
                ldsm4(f0, f1, f2, f3, bifp + kc * 32);
                ldsm4(g0, g1, g2, g3, bgop + kc * 32);
                mma_f16(dIF[0][0], dIF[0][1], dIF[0][2], dIF[0][3], ahi[kc], f0, f1);
                mma_f16(dIF[0][0], dIF[0][1], dIF[0][2], dIF[0][3], alo[kc], f0, f1);
                mma_f16(dIF[1][0], dIF[1][1], dIF[1][2], dIF[1][3], ahi[kc], f2, f3);
                mma_f16(dIF[1][0], dIF[1][1], dIF[1][2], dIF[1][3], alo[kc], f2, f3);
                mma_f16(dGO[0][0], dGO[0][1], dGO[0][2], dGO[0][3], ahi[kc], g0, g1);
                mma_f16(dGO[0][0], dGO[0][1], dGO[0][2], dGO[0][3], alo[kc], g0, g1);
                mma_f16(dGO[1][0], dGO[1][1], dGO[1][2], dGO[1][3], ahi[kc], g2, g3);
                mma_f16(dGO[1][0], dGO[1][1], dGO[1][2], dGO[1][3], alo[kc], g2, g3);
            }
            #pragma unroll
            for (int h2 = 0; h2 < 2; h2++){
                const int n0 = 2 * p + h2;
                const int j = cg * 24 + n0 * 4 + tg;
                const int rIF = cg * 48 + n0 * 8 + 2 * tg;        // IF col of i
                const int rGO = 192 + cg * 48 + n0 * 8 + 2 * tg;  // GO col of g
                float bi = bsd[rIF], bf = bsd[rIF + 1];
                float bg = bsd[rGO], bo = bsd[rGO + 1];
                float cnA = sigmf(dIF[h2][1] + bf) * c[2 * n0]
                          + sigmf(dIF[h2][0] + bi) * tanhf_(dGO[h2][0] + bg);
                float hA  = sigmf(dGO[h2][1] + bo) * tanhf_(cnA);
                c[2 * n0] = cnA;
                float cnB = sigmf(dIF[h2][3] + bf) * c[2 * n0 + 1]
                          + sigmf(dIF[h2][2] + bi) * tanhf_(dGO[h2][2] + bg);
                float hB  = sigmf(dGO[h2][3] + bo) * tanhf_(cnB);
                c[2 * n0 + 1] = cnB;
                __half hAh = __float2half_rn(hA);
                __half hBh = __float2half_rn(hB);
                *(__half*)(smc + SH_HI + woff + (eA * 104 + j) * 2) = hAh;
                *(__half*)(smc + SH_HI + woff + (eB * 104 + j) * 2) = hBh;
                *(__half*)(smc + SH_LO + woff + (eA * 104 + j) * 2) = __float2half_rn(hA - __half2float(hAh));
                *(__half*)(smc + SH_LO + woff + (eB * 104 + j) * 2) = __float2half_rn(hB - __half2float(hBh));
            }
        }
        __syncthreads();   // single barrier: h_t visible for pos + next step

        if (tid < 64){
            u64 ax = 0ULL, ay = 0ULL;
            const __half2* ph = (const __half2*)(smc + SH_HI + woff + tid * WROW);
            const __half2* pl = (const __half2*)(smc + SH_LO + woff + tid * WROW);
            #pragma unroll 8
            for (int kk = 0; kk < 48; kk++){
                float2 hi = __half22float2(ph[kk]);
                float2 lo = __half22float2(pl[kk]);
                u64 hd = pk2(hi.x + lo.x, hi.y + lo.y);
                ffma2(ax, hd, *(const u64*)&wex[2 * kk]);
                ffma2(ay, hd, *(const u64*)&wey[2 * kk]);
            }
            float2 o; o.x = red2(ax) + bex; o.y = red2(ay) + bey;
            *(float2*)(out + (b0 + tid) * 60 + 2 * t) = o;
        }
    }
}

extern "C" void kernel_launch(void* const* d_in, const int* in_sizes, int n_in,
                              void* d_out, int out_size)
{
    (void)n_in; (void)out_size;
    const float* traj  = (const float*)d_in[0];
    const float* cent  = (const float*)d_in[1];
    const float* Wih_c = (const float*)d_in[2];
    const float* Whh_c = (const float*)d_in[3];
    const float* bih_c = (const float*)d_in[4];
    const float* bhh_c = (const float*)d_in[5];
    const float* Wih_e = (const float*)d_in[6];
    const float* Whh_e = (const float*)d_in[7];
    const float* bih_e = (const float*)d_in[8];
    const float* bhh_e = (const float*)d_in[9];
    const float* Wih_d = (const float*)d_in[10];
    const float* Whh_d = (const float*)d_in[11];
    const float* bih_d = (const float*)d_in[12];
    const float* bhh_d = (const float*)d_in[13];
    const float* W_emb = (const float*)d_in[14];
    const float* b_emb = (const float*)d_in[15];
    float* out = (float*)d_out;

    const int B = in_sizes[0] / 40;   // input_traj [B][20][2]

    // SMEM bytes: G*KP*2 (W) + 4*64*KP*2 (h hi/lo x 2 buf)
    const int smc_b = 128*56*2 + 4*64*56*2;   //  43,008 (H=32, KP=56)
    const int sme_b = 256*88*2 + 4*64*88*2;   //  90,112 (H=64, KP=88)

    cudaFuncSetAttribute(lstm_rec_mma<32,100,64,2>, cudaFuncAttributeMaxDynamicSharedMemorySize, smc_b);
    cudaFuncSetAttribute(lstm_rec_mma<64, 20, 0,1>, cudaFuncAttributeMaxDynamicSharedMemorySize, sme_b);
    cudaFuncSetAttribute(lstm_dec_mma, cudaFuncAttributeMaxDynamicSharedMemorySize, SM_TOT);

    // centerline LSTM (H=32, T=100) -> g_h0/g_c0[.., 64..95]  (2 CTAs/SM)
    lstm_rec_mma<32,100,64,2><<<B / 64, 512, smc_b>>>(cent, Wih_c, Whh_c, bih_c, bhh_c);
    // encoder LSTM (H=64, T=20)    -> g_h0/g_c0[.., 0..63]
    lstm_rec_mma<64, 20, 0,1><<<B / 64, 512, sme_b>>>(traj, Wih_e, Whh_e, bih_e, bhh_e);
    // decoder (H=96, 30 steps, 64 elems/CTA) -> out [B][30][2]
    lstm_dec_mma<<<B / 64, DNT, SM_TOT>>>(Wih_d, Whh_d, bih_d, bhh_d, W_emb, b_emb, out);
}